// round 2
// baseline (speedup 1.0000x reference)
#include <cuda_runtime.h>

#define NC 80
#define CH 85
#define NB 16      // batch
#define NM 64      // boxes per image
#define NA 3       // anchors per layer

// Layer sizes
#define N0 307200  // 16*3*80*80
#define N1 76800   // 16*3*40*40
#define N2 19200   // 16*3*20*20
#define BLK0 300   // N0 / (256*4)
#define BLK1 75
#define BLK2 19    // ceil(19200/1024)
#define NBLK (BLK0 + BLK1 + BLK2)   // 394

__device__ float g_cls[3];
__device__ float g_bbox[3];
__device__ float g_corr[3];
__device__ int   g_npos[3];
__device__ float g_obj_part[NBLK];

__device__ __forceinline__ float softplus0(float x) {
    // BCE(x, 0) = max(x,0) + log1p(exp(-|x|))
    return fmaxf(x, 0.0f) + log1pf(__expf(-fabsf(x)));
}

// ---------------------------------------------------------------------------
// Kernel 1: per-box work. 3 blocks (one per layer) x 1024 threads (B*M).
// ---------------------------------------------------------------------------
__global__ void box_kernel(const float* __restrict__ p3,
                           const float* __restrict__ p4,
                           const float* __restrict__ p5,
                           const float* __restrict__ boxes,
                           const int*   __restrict__ labels,
                           const unsigned char* __restrict__ valid,
                           const float* __restrict__ anchors)
{
    const int l = blockIdx.x;
    const int g = (l == 0) ? 80 : (l == 1) ? 40 : 20;
    const float* pred = (l == 0) ? p3 : (l == 1) ? p4 : p5;

    const int tid = threadIdx.x;         // 0..1023 == b*64 + m
    const int b = tid >> 6;

    __shared__ int table[2048];
    __shared__ float s_f[3][32];
    __shared__ int s_i[32];

    for (int i = tid; i < 2048; i += 1024) table[i] = -1;

    float aw0 = anchors[l * 6 + 0], ah0 = anchors[l * 6 + 1];
    float aw1 = anchors[l * 6 + 2], ah1 = anchors[l * 6 + 3];
    float aw2 = anchors[l * 6 + 4], ah2 = anchors[l * 6 + 5];

    const float4 bx = ((const float4*)boxes)[tid];
    const float gf = (float)g;
    float cx = (bx.x + bx.z) * 0.5f * gf;
    float cy = (bx.y + bx.w) * 0.5f * gf;
    float w  = (bx.z - bx.x) * gf;
    float h  = (bx.w - bx.y) * gf;

    float wh = w * h;
    float i0 = fminf(w, aw0) * fminf(h, ah0);
    float i1 = fminf(w, aw1) * fminf(h, ah1);
    float i2 = fminf(w, aw2) * fminf(h, ah2);
    float iou0 = i0 / (wh + aw0 * ah0 - i0 + 1e-6f);
    float iou1 = i1 / (wh + aw1 * ah1 - i1 + 1e-6f);
    float iou2 = i2 / (wh + aw2 * ah2 - i2 + 1e-6f);

    int besta = 0; float bi = iou0;
    if (iou1 > bi) { bi = iou1; besta = 1; }
    if (iou2 > bi) { bi = iou2; besta = 2; }

    const bool pos = (valid[tid] != 0) && (bi > 0.5f);
    int gx = min(max((int)cx, 0), g - 1);
    int gy = min(max((int)cy, 0), g - 1);
    const int key = ((b * NA + besta) * g + gy) * g + gx;

    __syncthreads();   // table init complete

    float cls = 0.0f, bbox = 0.0f, corr = 0.0f;
    int np = 0;

    if (pos) {
        np = 1;
        const float* pp = pred + (size_t)key * CH;

        // --- dedup: first thread to claim this cell applies obj correction ---
        bool first = false;
        unsigned hsh = ((unsigned)key * 2654435761u) & 2047u;
        while (true) {
            int old = atomicCAS(&table[hsh], -1, key);
            if (old == -1) { first = true; break; }
            if (old == key) { first = false; break; }
            hsh = (hsh + 1u) & 2047u;
        }
        if (first) corr = -pp[4];   // BCE(x,1) - BCE(x,0) == -x

        // --- cls: sum softplus over 80 classes, minus logit at the label ---
        int lab = labels[tid];
        float cs = 0.0f;
        #pragma unroll 4
        for (int c = 0; c < NC; c++) cs += softplus0(pp[5 + c]);
        cs -= pp[5 + lab];
        cls = cs;

        // --- CIoU (exact replication of reference arithmetic) ---
        float pcx = pp[0], pcy = pp[1], pw = pp[2], ph = pp[3];
        float px1 = pcx - pw * 0.5f, py1 = pcy - ph * 0.5f;
        float px2 = pcx + pw * 0.5f, py2 = pcy + ph * 0.5f;
        float tx1 = cx - w * 0.5f, ty1 = cy - h * 0.5f;
        float tx2 = cx + w * 0.5f, ty2 = cy + h * 0.5f;
        float ix1 = fmaxf(px1, tx1), iy1 = fmaxf(py1, ty1);
        float ix2 = fminf(px2, tx2), iy2 = fminf(py2, ty2);
        float inter = fmaxf(ix2 - ix1, 0.0f) * fmaxf(iy2 - iy1, 0.0f);
        float a1 = (px2 - px1) * (py2 - py1);
        float a2 = (tx2 - tx1) * (ty2 - ty1);
        float iou = inter / (a1 + a2 - inter + 1e-7f);
        float ccx = (px1 + px2) * 0.5f, ccy = (py1 + py2) * 0.5f;
        float dcx = (tx1 + tx2) * 0.5f, dcy = (ty1 + ty2) * 0.5f;
        float cd = (ccx - dcx) * (ccx - dcx) + (ccy - dcy) * (ccy - dcy);
        float ex1 = fminf(px1, tx1), ey1 = fminf(py1, ty1);
        float ex2 = fmaxf(px2, tx2), ey2 = fmaxf(py2, ty2);
        float dd = (ex2 - ex1) * (ex2 - ex1) + (ey2 - ey1) * (ey2 - ey1);
        bbox = 1.0f - (iou - cd / (dd + 1e-7f));
    }

    // --- block reduction: cls, bbox, corr (float) + np (int) ---
    #pragma unroll
    for (int o = 16; o > 0; o >>= 1) {
        cls  += __shfl_down_sync(0xffffffffu, cls,  o);
        bbox += __shfl_down_sync(0xffffffffu, bbox, o);
        corr += __shfl_down_sync(0xffffffffu, corr, o);
        np   += __shfl_down_sync(0xffffffffu, np,   o);
    }
    const int wid = tid >> 5, lid = tid & 31;
    if (lid == 0) { s_f[0][wid] = cls; s_f[1][wid] = bbox; s_f[2][wid] = corr; s_i[wid] = np; }
    __syncthreads();
    if (wid == 0) {
        cls  = s_f[0][lid];
        bbox = s_f[1][lid];
        corr = s_f[2][lid];
        np   = s_i[lid];
        #pragma unroll
        for (int o = 16; o > 0; o >>= 1) {
            cls  += __shfl_down_sync(0xffffffffu, cls,  o);
            bbox += __shfl_down_sync(0xffffffffu, bbox, o);
            corr += __shfl_down_sync(0xffffffffu, corr, o);
            np   += __shfl_down_sync(0xffffffffu, np,   o);
        }
        if (lid == 0) {
            g_cls[l] = cls; g_bbox[l] = bbox; g_corr[l] = corr; g_npos[l] = np;
        }
    }
}

// ---------------------------------------------------------------------------
// Kernel 2: streaming softplus over objectness channel of all 3 layers.
// 394 blocks x 256 threads, 4 elements per thread. Per-block partial sums
// to a global array (no atomics -> deterministic).
// ---------------------------------------------------------------------------
__global__ void obj_kernel(const float* __restrict__ p3,
                           const float* __restrict__ p4,
                           const float* __restrict__ p5)
{
    const int bid = blockIdx.x;
    const float* p; int n, lb;
    if (bid < BLK0)              { p = p3; n = N0; lb = bid; }
    else if (bid < BLK0 + BLK1)  { p = p4; n = N1; lb = bid - BLK0; }
    else                         { p = p5; n = N2; lb = bid - BLK0 - BLK1; }

    const int tid = threadIdx.x;
    const int base = lb * 1024 + tid;

    float s = 0.0f;
    #pragma unroll
    for (int k = 0; k < 4; k++) {
        int i = base + k * 256;
        if (i < n) {
            float x = __ldg(&p[(size_t)i * CH + 4]);
            s += fmaxf(x, 0.0f) + log1pf(__expf(-fabsf(x)));
        }
    }

    __shared__ float s_p[8];
    #pragma unroll
    for (int o = 16; o > 0; o >>= 1) s += __shfl_down_sync(0xffffffffu, s, o);
    const int wid = tid >> 5, lid = tid & 31;
    if (lid == 0) s_p[wid] = s;
    __syncthreads();
    if (wid == 0) {
        s = (lid < 8) ? s_p[lid] : 0.0f;
        #pragma unroll
        for (int o = 4; o > 0; o >>= 1) s += __shfl_down_sync(0xffffffffu, s, o);
        if (lid == 0) g_obj_part[bid] = s;
    }
}

// ---------------------------------------------------------------------------
// Kernel 3: finalize. One warp sums obj partials per layer and combines.
// ---------------------------------------------------------------------------
__global__ void fin_kernel(float* __restrict__ out)
{
    const int lid = threadIdx.x;   // 32 threads
    const int start[4] = {0, BLK0, BLK0 + BLK1, NBLK};
    const float cells[3] = {(float)N0, (float)N1, (float)N2};

    float osum[3];
    #pragma unroll
    for (int l = 0; l < 3; l++) {
        float s = 0.0f;
        for (int i = start[l] + lid; i < start[l + 1]; i += 32)
            s += g_obj_part[i];
        #pragma unroll
        for (int o = 16; o > 0; o >>= 1) s += __shfl_down_sync(0xffffffffu, s, o);
        osum[l] = s;   // valid on lane 0
    }

    if (lid == 0) {
        float tot = 0.0f;
        #pragma unroll
        for (int l = 0; l < 3; l++) {
            int np = g_npos[l];
            if (np > 0) {
                float d = (float)np;
                float cls  = g_cls[l] / (d * (float)NC);
                float obj  = (osum[l] + g_corr[l]) / cells[l];
                float bbox = g_bbox[l] / d;
                tot += 0.5f * cls + obj + 0.05f * bbox;
            }
        }
        out[0] = tot;
    }
}

extern "C" void kernel_launch(void* const* d_in, const int* in_sizes, int n_in,
                              void* d_out, int out_size)
{
    const float* p3     = (const float*)d_in[0];
    const float* p4     = (const float*)d_in[1];
    const float* p5     = (const float*)d_in[2];
    const float* boxes  = (const float*)d_in[3];
    const int*   labels = (const int*)d_in[4];
    const unsigned char* valid = (const unsigned char*)d_in[5];
    const float* anchors = (const float*)d_in[6];

    box_kernel<<<3, 1024>>>(p3, p4, p5, boxes, labels, valid, anchors);
    obj_kernel<<<NBLK, 256>>>(p3, p4, p5);
    fin_kernel<<<1, 32>>>((float*)d_out);
}

// round 3
// speedup vs baseline: 1.7945x; 1.7945x over previous
#include <cuda_runtime.h>

#define NC 80
#define CH 85
#define NB 16      // batch
#define NM 64      // boxes per image
#define NA 3       // anchors per layer

// Layer sizes
#define N0 307200  // 16*3*80*80
#define N1 76800   // 16*3*40*40
#define N2 19200   // 16*3*20*20
#define BLK0 300   // N0 / (256*4)
#define BLK1 75
#define BLK2 19    // ceil(19200/1024)
#define NBLK (BLK0 + BLK1 + BLK2)   // 394

#define NBOXBLK 48  // 3 layers * 16 batch

__device__ float4 g_box_part[NBOXBLK];   // {cls, bbox, corr, npos} per (layer,b) block
__device__ float  g_obj_part[NBLK];

__device__ __forceinline__ float softplus0(float x) {
    // BCE(x, 0) = max(x,0) + log1p(exp(-|x|))
    return fmaxf(x, 0.0f) + log1pf(__expf(-fabsf(x)));
}

// ---------------------------------------------------------------------------
// Kernel 1: per-box work. 48 blocks = (layer, b) x 1024 threads.
// Each box owned by 16 threads; each thread handles 5 class channels.
// All loss terms are global sums, so we reduce the whole block directly.
// ---------------------------------------------------------------------------
__global__ void __launch_bounds__(1024, 1)
box_kernel(const float* __restrict__ p3,
           const float* __restrict__ p4,
           const float* __restrict__ p5,
           const float* __restrict__ boxes,
           const int*   __restrict__ labels,
           const unsigned char* __restrict__ valid,
           const float* __restrict__ anchors)
{
    const int l = blockIdx.x >> 4;       // layer
    const int b = blockIdx.x & 15;       // batch image
    const int g = (l == 0) ? 80 : (l == 1) ? 40 : 20;
    const float* pred = (l == 0) ? p3 : (l == 1) ? p4 : p5;

    const int tid = threadIdx.x;
    const int m   = tid >> 4;            // box 0..63
    const int sub = tid & 15;            // sub-lane 0..15

    __shared__ int table[256];
    __shared__ float s_f[4][32];

    if (tid < 256) table[tid] = -1;

    const float aw0 = anchors[l * 6 + 0], ah0 = anchors[l * 6 + 1];
    const float aw1 = anchors[l * 6 + 2], ah1 = anchors[l * 6 + 3];
    const float aw2 = anchors[l * 6 + 4], ah2 = anchors[l * 6 + 5];

    const int bm = b * NM + m;
    const float4 bx = ((const float4*)boxes)[bm];
    const float gf = (float)g;
    const float cx = (bx.x + bx.z) * 0.5f * gf;
    const float cy = (bx.y + bx.w) * 0.5f * gf;
    const float w  = (bx.z - bx.x) * gf;
    const float h  = (bx.w - bx.y) * gf;

    const float wh = w * h;
    const float i0 = fminf(w, aw0) * fminf(h, ah0);
    const float i1 = fminf(w, aw1) * fminf(h, ah1);
    const float i2 = fminf(w, aw2) * fminf(h, ah2);
    const float iou0 = i0 / (wh + aw0 * ah0 - i0 + 1e-6f);
    const float iou1 = i1 / (wh + aw1 * ah1 - i1 + 1e-6f);
    const float iou2 = i2 / (wh + aw2 * ah2 - i2 + 1e-6f);

    int besta = 0; float bi = iou0;
    if (iou1 > bi) { bi = iou1; besta = 1; }
    if (iou2 > bi) { bi = iou2; besta = 2; }

    const bool pos = (valid[bm] != 0) && (bi > 0.5f);
    const int gx = min(max((int)cx, 0), g - 1);
    const int gy = min(max((int)cy, 0), g - 1);
    const int key = ((b * NA + besta) * g + gy) * g + gx;

    __syncthreads();   // table init complete

    float cls = 0.0f, bbox = 0.0f, corr = 0.0f, np = 0.0f;

    if (pos) {
        const float* pp = pred + (size_t)key * CH;

        // --- cls: this thread's 5 of the 80 class channels ---
        #pragma unroll
        for (int k = 0; k < 5; k++) cls += softplus0(pp[5 + sub + 16 * k]);

        if (sub == 0) {
            np = 1.0f;
            cls -= pp[5 + labels[bm]];   // subtract logit at the label

            // --- dedup: first thread to claim this cell applies obj correction ---
            bool first = false;
            unsigned hsh = ((unsigned)key * 2654435761u) & 255u;
            while (true) {
                int old = atomicCAS(&table[hsh], -1, key);
                if (old == -1) { first = true; break; }
                if (old == key) { break; }
                hsh = (hsh + 1u) & 255u;
            }
            if (first) corr = -pp[4];    // BCE(x,1) - BCE(x,0) == -x

            // --- CIoU (exact replication of reference arithmetic) ---
            float pcx = pp[0], pcy = pp[1], pw = pp[2], ph = pp[3];
            float px1 = pcx - pw * 0.5f, py1 = pcy - ph * 0.5f;
            float px2 = pcx + pw * 0.5f, py2 = pcy + ph * 0.5f;
            float tx1 = cx - w * 0.5f, ty1 = cy - h * 0.5f;
            float tx2 = cx + w * 0.5f, ty2 = cy + h * 0.5f;
            float ix1 = fmaxf(px1, tx1), iy1 = fmaxf(py1, ty1);
            float ix2 = fminf(px2, tx2), iy2 = fminf(py2, ty2);
            float inter = fmaxf(ix2 - ix1, 0.0f) * fmaxf(iy2 - iy1, 0.0f);
            float a1 = (px2 - px1) * (py2 - py1);
            float a2 = (tx2 - tx1) * (ty2 - ty1);
            float iou = inter / (a1 + a2 - inter + 1e-7f);
            float ccx = (px1 + px2) * 0.5f, ccy = (py1 + py2) * 0.5f;
            float dcx = (tx1 + tx2) * 0.5f, dcy = (ty1 + ty2) * 0.5f;
            float cd = (ccx - dcx) * (ccx - dcx) + (ccy - dcy) * (ccy - dcy);
            float ex1 = fminf(px1, tx1), ey1 = fminf(py1, ty1);
            float ex2 = fmaxf(px2, tx2), ey2 = fmaxf(py2, ty2);
            float dd = (ex2 - ex1) * (ex2 - ex1) + (ey2 - ey1) * (ey2 - ey1);
            bbox = 1.0f - (iou - cd / (dd + 1e-7f));
        }
    }

    // --- block reduction of {cls, bbox, corr, np} ---
    #pragma unroll
    for (int o = 16; o > 0; o >>= 1) {
        cls  += __shfl_down_sync(0xffffffffu, cls,  o);
        bbox += __shfl_down_sync(0xffffffffu, bbox, o);
        corr += __shfl_down_sync(0xffffffffu, corr, o);
        np   += __shfl_down_sync(0xffffffffu, np,   o);
    }
    const int wid = tid >> 5, lid = tid & 31;
    if (lid == 0) { s_f[0][wid] = cls; s_f[1][wid] = bbox; s_f[2][wid] = corr; s_f[3][wid] = np; }
    __syncthreads();
    if (wid == 0) {
        cls  = s_f[0][lid];
        bbox = s_f[1][lid];
        corr = s_f[2][lid];
        np   = s_f[3][lid];
        #pragma unroll
        for (int o = 16; o > 0; o >>= 1) {
            cls  += __shfl_down_sync(0xffffffffu, cls,  o);
            bbox += __shfl_down_sync(0xffffffffu, bbox, o);
            corr += __shfl_down_sync(0xffffffffu, corr, o);
            np   += __shfl_down_sync(0xffffffffu, np,   o);
        }
        if (lid == 0) g_box_part[blockIdx.x] = make_float4(cls, bbox, corr, np);
    }
}

// ---------------------------------------------------------------------------
// Kernel 2: streaming softplus over objectness channel of all 3 layers.
// ---------------------------------------------------------------------------
__global__ void obj_kernel(const float* __restrict__ p3,
                           const float* __restrict__ p4,
                           const float* __restrict__ p5)
{
    const int bid = blockIdx.x;
    const float* p; int n, lb;
    if (bid < BLK0)              { p = p3; n = N0; lb = bid; }
    else if (bid < BLK0 + BLK1)  { p = p4; n = N1; lb = bid - BLK0; }
    else                         { p = p5; n = N2; lb = bid - BLK0 - BLK1; }

    const int tid = threadIdx.x;
    const int base = lb * 1024 + tid;

    float s = 0.0f;
    #pragma unroll
    for (int k = 0; k < 4; k++) {
        int i = base + k * 256;
        if (i < n) {
            float x = __ldg(&p[(size_t)i * CH + 4]);
            s += fmaxf(x, 0.0f) + log1pf(__expf(-fabsf(x)));
        }
    }

    __shared__ float s_p[8];
    #pragma unroll
    for (int o = 16; o > 0; o >>= 1) s += __shfl_down_sync(0xffffffffu, s, o);
    const int wid = tid >> 5, lid = tid & 31;
    if (lid == 0) s_p[wid] = s;
    __syncthreads();
    if (wid == 0) {
        s = (lid < 8) ? s_p[lid] : 0.0f;
        #pragma unroll
        for (int o = 4; o > 0; o >>= 1) s += __shfl_down_sync(0xffffffffu, s, o);
        if (lid == 0) g_obj_part[bid] = s;
    }
}

// ---------------------------------------------------------------------------
// Kernel 3: finalize. One warp: per-layer sums, combine.
// ---------------------------------------------------------------------------
__global__ void fin_kernel(float* __restrict__ out)
{
    const int lid = threadIdx.x;   // 32 threads
    const int start[4] = {0, BLK0, BLK0 + BLK1, NBLK};
    const float cells[3] = {(float)N0, (float)N1, (float)N2};

    float tot = 0.0f;
    #pragma unroll
    for (int l = 0; l < 3; l++) {
        // obj partial sums for this layer
        float s = 0.0f;
        for (int i = start[l] + lid; i < start[l + 1]; i += 32)
            s += g_obj_part[i];
        // box partials: 16 blocks for this layer
        float cls = 0.0f, bbox = 0.0f, corr = 0.0f, np = 0.0f;
        if (lid < 16) {
            float4 v = g_box_part[l * 16 + lid];
            cls = v.x; bbox = v.y; corr = v.z; np = v.w;
        }
        #pragma unroll
        for (int o = 16; o > 0; o >>= 1) {
            s    += __shfl_down_sync(0xffffffffu, s,    o);
            cls  += __shfl_down_sync(0xffffffffu, cls,  o);
            bbox += __shfl_down_sync(0xffffffffu, bbox, o);
            corr += __shfl_down_sync(0xffffffffu, corr, o);
            np   += __shfl_down_sync(0xffffffffu, np,   o);
        }
        if (lid == 0 && np > 0.0f) {
            float d = np;
            tot += 0.5f  * (cls / (d * (float)NC))
                 +         ((s + corr) / cells[l])
                 + 0.05f * (bbox / d);
        }
    }
    if (lid == 0) out[0] = tot;
}

extern "C" void kernel_launch(void* const* d_in, const int* in_sizes, int n_in,
                              void* d_out, int out_size)
{
    const float* p3     = (const float*)d_in[0];
    const float* p4     = (const float*)d_in[1];
    const float* p5     = (const float*)d_in[2];
    const float* boxes  = (const float*)d_in[3];
    const int*   labels = (const int*)d_in[4];
    const unsigned char* valid = (const unsigned char*)d_in[5];
    const float* anchors = (const float*)d_in[6];

    box_kernel<<<NBOXBLK, 1024>>>(p3, p4, p5, boxes, labels, valid, anchors);
    obj_kernel<<<NBLK, 256>>>(p3, p4, p5);
    fin_kernel<<<1, 32>>>((float*)d_out);
}